// round 14
// baseline (speedup 1.0000x reference)
#include <cuda_runtime.h>
#include <math_constants.h>
#include <cstdint>

// Problem constants
constexpr int B = 32, S = 4, K = 11, C = 9, H = 128, W = 128;
constexpr int HW = H * W;          // 16384
constexpr int BSK = B * S * K;     // 1408 planes
constexpr int BS = B * S;          // 128
constexpr int NSPL = 2;            // blocks per plane -> grid = 2816
constexpr int CH8 = HW / 8;        // 2048 8-float chunks per plane
constexpr int CH8H = CH8 / NSPL;   // 1024 chunks per half

// Cross-block scratch (device globals; zeroed by init kernel each launch,
// counter is monotonic with mod-NSPL arrival detection).
__device__ float              g_sq[BSK];
__device__ unsigned long long g_amax[BSK];
__device__ unsigned int       g_cnt[BSK];

// orderable-float key: monotone map float -> uint32 (total order)
__device__ __forceinline__ unsigned int fkey(float v) {
    unsigned int u = __float_as_uint(v);
    return (u & 0x80000000u) ? ~u : (u | 0x80000000u);
}
__device__ __forceinline__ float fkey_inv(unsigned int key) {
    unsigned int u = (key & 0x80000000u) ? (key & 0x7FFFFFFFu) : ~key;
    return __uint_as_float(u);
}

// Zero scratch + output every launch.
__global__ __launch_bounds__(256) void kp_zero_kernel(float* __restrict__ out) {
    const int t = blockIdx.x * 256 + threadIdx.x;
    if (t < 2 * BS) out[t] = 0.0f;
    if (t < BSK) { g_sq[t] = 0.0f; g_amax[t] = 0ULL; }
}

// 32-byte loads (sm_103a .v4.b64 class — required width for L2 hint forms).
__device__ __forceinline__ void ldg_evict_last8(const float* p,
                                                float4& a, float4& b) {
    uint64_t r0, r1, r2, r3;
    asm volatile("ld.global.nc.L2::evict_last.v4.b64 {%0,%1,%2,%3}, [%4];"
                 : "=l"(r0), "=l"(r1), "=l"(r2), "=l"(r3) : "l"(p));
    a.x = __uint_as_float((uint32_t)r0); a.y = __uint_as_float((uint32_t)(r0 >> 32));
    a.z = __uint_as_float((uint32_t)r1); a.w = __uint_as_float((uint32_t)(r1 >> 32));
    b.x = __uint_as_float((uint32_t)r2); b.y = __uint_as_float((uint32_t)(r2 >> 32));
    b.z = __uint_as_float((uint32_t)r3); b.w = __uint_as_float((uint32_t)(r3 >> 32));
}
__device__ __forceinline__ void ldg_evict_first8(const float* p,
                                                 float4& a, float4& b) {
    uint64_t r0, r1, r2, r3;
    asm volatile("ld.global.nc.L2::evict_first.v4.b64 {%0,%1,%2,%3}, [%4];"
                 : "=l"(r0), "=l"(r1), "=l"(r2), "=l"(r3) : "l"(p));
    a.x = __uint_as_float((uint32_t)r0); a.y = __uint_as_float((uint32_t)(r0 >> 32));
    a.z = __uint_as_float((uint32_t)r1); a.w = __uint_as_float((uint32_t)(r1 >> 32));
    b.x = __uint_as_float((uint32_t)r2); b.y = __uint_as_float((uint32_t)(r2 >> 32));
    b.z = __uint_as_float((uint32_t)r3); b.w = __uint_as_float((uint32_t)(r3 >> 32));
}

// grid = BSK * NSPL: block (plane blk, half h) streams half the plane.
// 2nd-arriving block per plane combines halves + runs the label epilogue.
__global__ __launch_bounds__(256) void kp_fused_kernel(
    const float* __restrict__ hm_preds,   // [B,S,K,H,W]
    const float* __restrict__ lb_preds,   // [B,S,C,H,W]
    const float* __restrict__ heatmaps,   // [B,K,H,W]
    const float* __restrict__ labels,     // [B,K,11]
    float* __restrict__ out)              // [2*B*S]: [hm | lb]
{
    const int bid = blockIdx.x;
    const int blk = bid >> 1;             // plane: b*S*K + s*K + k
    const int hf  = bid & 1;              // half of the plane
    const int k = blk % K;
    const int bs = blk / K;               // b*S + s
    const int b = bs / S;

    const float* __restrict__ p = hm_preds + (size_t)blk * HW;
    const float* __restrict__ g = heatmaps + ((size_t)b * K + k) * HW;

    const int tid = threadIdx.x;

    float sq = 0.0f;
    float mx = -CUDART_INF_F;
    int   mi = 0;

    // 1024 chunks per half, 256 threads -> 4 iterations/thread.
    const int ibase = hf * CH8H;
    #pragma unroll
    for (int it = 0; it < CH8H / 256; it++) {
        const int i = ibase + it * 256 + tid;
        float4 g0, g1, p0, p1;
        ldg_evict_last8(g + (size_t)i * 8, g0, g1);
        ldg_evict_first8(p + (size_t)i * 8, p0, p1);

        float d0 = p0.x - g0.x, d1 = p0.y - g0.y;
        float d2 = p0.z - g0.z, d3 = p0.w - g0.w;
        float e0 = p1.x - g1.x, e1 = p1.y - g1.y;
        float e2 = p1.z - g1.z, e3 = p1.w - g1.w;
        sq += d0 * d0 + d1 * d1 + d2 * d2 + d3 * d3;
        sq += e0 * e0 + e1 * e1 + e2 * e2 + e3 * e3;

        const int base = i * 8;
        // strict > keeps the lowest index within this thread (indices ascend)
        if (p0.x > mx) { mx = p0.x; mi = base;     }
        if (p0.y > mx) { mx = p0.y; mi = base + 1; }
        if (p0.z > mx) { mx = p0.z; mi = base + 2; }
        if (p0.w > mx) { mx = p0.w; mi = base + 3; }
        if (p1.x > mx) { mx = p1.x; mi = base + 4; }
        if (p1.y > mx) { mx = p1.y; mi = base + 5; }
        if (p1.z > mx) { mx = p1.z; mi = base + 6; }
        if (p1.w > mx) { mx = p1.w; mi = base + 7; }
    }

    // Warp reduction (sum + argmax with first-index tiebreak)
    #pragma unroll
    for (int off = 16; off > 0; off >>= 1) {
        sq += __shfl_down_sync(0xFFFFFFFFu, sq, off);
        float omx = __shfl_down_sync(0xFFFFFFFFu, mx, off);
        int   omi = __shfl_down_sync(0xFFFFFFFFu, mi, off);
        if (omx > mx || (omx == mx && omi < mi)) { mx = omx; mi = omi; }
    }

    __shared__ float s_sq[8];
    __shared__ float s_mx[8];
    __shared__ int   s_mi[8];
    const int wid = tid >> 5, lane = tid & 31;
    if (lane == 0) { s_sq[wid] = sq; s_mx[wid] = mx; s_mi[wid] = mi; }
    __syncthreads();

    if (wid == 0) {
        sq = (lane < 8) ? s_sq[lane] : 0.0f;
        mx = (lane < 8) ? s_mx[lane] : -CUDART_INF_F;
        mi = (lane < 8) ? s_mi[lane] : 0x7FFFFFFF;
        #pragma unroll
        for (int off = 4; off > 0; off >>= 1) {
            sq += __shfl_down_sync(0xFFFFFFFFu, sq, off);
            float omx = __shfl_down_sync(0xFFFFFFFFu, mx, off);
            int   omi = __shfl_down_sync(0xFFFFFFFFu, mi, off);
            if (omx > mx || (omx == mx && omi < mi)) { mx = omx; mi = omi; }
        }

        // Publish half-plane partials; detect 2nd arrival.
        int last = 0;
        if (lane == 0) {
            atomicAdd(&g_sq[blk], sq);   // exactly 2 addends: order-invariant
            const unsigned long long packed =
                ((unsigned long long)fkey(mx) << 32) |
                (unsigned long long)(0xFFFFFFFFu - (unsigned int)mi);
            atomicMax(&g_amax[blk], packed);
            __threadfence();
            const unsigned int old = atomicAdd(&g_cnt[blk], 1u);
            last = ((old & 1u) == 1u);   // 2nd arrival this launch
        }
        last = __shfl_sync(0xFFFFFFFFu, last, 0);
        if (!last) return;
        __threadfence();                 // see peer's published partials

        // ---- Plane epilogue: combined sumsq + argmax -> label loss ----
        const float hsum = __ldcg(&g_sq[blk]);
        const unsigned long long packed = __ldcg(&g_amax[blk]);
        const float conf = fkey_inv((unsigned int)(packed >> 32));
        const int   fmi  = (int)(0xFFFFFFFFu - (unsigned int)packed);

        const float* __restrict__ lab = labels + ((size_t)b * K + k) * 11;

        // lanes 0..8: one class-channel gather each at the argmax position
        float part = 0.0f;
        if (lane < C) {
            const float v = __ldg(&lb_preds[((size_t)bs * C + lane) * HW + fmi]);
            const float d = v - __ldg(&lab[lane]);
            part = d * d;
        }
        #pragma unroll
        for (int off = 8; off > 0; off >>= 1)
            part += __shfl_down_sync(0xFFFFFFFFu, part, off);

        if (lane == 0) {
            const float gx = __ldg(&lab[9]);
            const float gy = __ldg(&lab[10]);
            const bool valid = (gx >= 0.0f) && (gy >= 0.0f) &&
                               (gx < (float)H) && (gy < (float)W);
            const int x = fmi / W;  // H == W == 128: pos == idx
            const int y = fmi % W;
            const float dx = gx - (float)x;
            const float dy = gy - (float)y;
            const float cf = 1.0f - conf;
            const float lb = valid ? (part + dx * dx + dy * dy + cf * cf) : 0.0f;

            atomicAdd(&out[bs],      hsum);  // hm_loss [B,S]
            atomicAdd(&out[BS + bs], lb);    // lb_loss [B,S]
        }
    }
}

extern "C" void kernel_launch(void* const* d_in, const int* in_sizes, int n_in,
                              void* d_out, int out_size) {
    const float* hm_preds = (const float*)d_in[0];  // [B,S,K,H,W]
    const float* lb_preds = (const float*)d_in[1];  // [B,S,C,H,W]
    const float* heatmaps = (const float*)d_in[2];  // [B,K,H,W]
    const float* labels   = (const float*)d_in[3];  // [B,K,11]
    float* out = (float*)d_out;

    kp_zero_kernel<<<(BSK + 255) / 256, 256>>>(out);
    kp_fused_kernel<<<BSK * NSPL, 256>>>(hm_preds, lb_preds, heatmaps, labels, out);
}

// round 15
// speedup vs baseline: 1.2092x; 1.2092x over previous
#include <cuda_runtime.h>
#include <math_constants.h>
#include <cstdint>

// Problem constants
constexpr int B = 32, S = 4, K = 11, C = 9, H = 128, W = 128;
constexpr int HW = H * W;          // 16384
constexpr int BSK = B * S * K;     // 1408
constexpr int BS = B * S;          // 128
constexpr int NT = 128;            // threads per block (4 warps)

// Zero-init the output (poisoned by harness; we accumulate with atomics).
__global__ __launch_bounds__(256) void kp_zero_kernel(float* __restrict__ out) {
    out[threadIdx.x] = 0.0f;       // exactly 2*BS = 256 elements
}

// 32-byte loads (sm_103a .v4.b64 class — required width for L2 hint forms).
// gt: evict_last (pin resident across graph replays).
// pred: evict_first (pure stream, don't pollute L2).
__device__ __forceinline__ void ldg_evict_last8(const float* p,
                                                float4& a, float4& b) {
    uint64_t r0, r1, r2, r3;
    asm volatile("ld.global.nc.L2::evict_last.v4.b64 {%0,%1,%2,%3}, [%4];"
                 : "=l"(r0), "=l"(r1), "=l"(r2), "=l"(r3) : "l"(p));
    a.x = __uint_as_float((uint32_t)r0); a.y = __uint_as_float((uint32_t)(r0 >> 32));
    a.z = __uint_as_float((uint32_t)r1); a.w = __uint_as_float((uint32_t)(r1 >> 32));
    b.x = __uint_as_float((uint32_t)r2); b.y = __uint_as_float((uint32_t)(r2 >> 32));
    b.z = __uint_as_float((uint32_t)r3); b.w = __uint_as_float((uint32_t)(r3 >> 32));
}
__device__ __forceinline__ void ldg_evict_first8(const float* p,
                                                 float4& a, float4& b) {
    uint64_t r0, r1, r2, r3;
    asm volatile("ld.global.nc.L2::evict_first.v4.b64 {%0,%1,%2,%3}, [%4];"
                 : "=l"(r0), "=l"(r1), "=l"(r2), "=l"(r3) : "l"(p));
    a.x = __uint_as_float((uint32_t)r0); a.y = __uint_as_float((uint32_t)(r0 >> 32));
    a.z = __uint_as_float((uint32_t)r1); a.w = __uint_as_float((uint32_t)(r1 >> 32));
    b.x = __uint_as_float((uint32_t)r2); b.y = __uint_as_float((uint32_t)(r2 >> 32));
    b.z = __uint_as_float((uint32_t)r3); b.w = __uint_as_float((uint32_t)(r3 >> 32));
}

// One 128-thread block per (b,s,k) plane: with ~34 regs this gives 16
// resident blocks/SM -> all 1408 blocks fit in ONE wave (no tail).
__global__ __launch_bounds__(NT) void kp_fused_kernel(
    const float* __restrict__ hm_preds,   // [B,S,K,H,W]
    const float* __restrict__ lb_preds,   // [B,S,C,H,W]
    const float* __restrict__ heatmaps,   // [B,K,H,W]
    const float* __restrict__ labels,     // [B,K,11]
    float* __restrict__ out)              // [2*B*S]: [hm | lb]
{
    const int blk = blockIdx.x;           // b*S*K + s*K + k
    const int k = blk % K;
    const int bs = blk / K;               // b*S + s
    const int b = bs / S;

    const float* __restrict__ p = hm_preds + (size_t)blk * HW;
    const float* __restrict__ g = heatmaps + ((size_t)b * K + k) * HW;

    const int tid = threadIdx.x;

    float sq = 0.0f;
    float mx = -CUDART_INF_F;
    int   mi = 0;

    // HW/8 = 2048 8-float chunks, 128 threads -> 16 iterations/thread.
    // Per iter: one 32B evict-last gt load + one 32B evict-first pred load.
    #pragma unroll 4
    for (int i = tid; i < HW / 8; i += NT) {
        float4 g0, g1, p0, p1;
        ldg_evict_last8(g + (size_t)i * 8, g0, g1);
        ldg_evict_first8(p + (size_t)i * 8, p0, p1);

        float d0 = p0.x - g0.x, d1 = p0.y - g0.y;
        float d2 = p0.z - g0.z, d3 = p0.w - g0.w;
        float e0 = p1.x - g1.x, e1 = p1.y - g1.y;
        float e2 = p1.z - g1.z, e3 = p1.w - g1.w;
        sq += d0 * d0 + d1 * d1 + d2 * d2 + d3 * d3;
        sq += e0 * e0 + e1 * e1 + e2 * e2 + e3 * e3;

        const int base = i * 8;
        // strict > keeps the lowest index within this thread (indices ascend)
        if (p0.x > mx) { mx = p0.x; mi = base;     }
        if (p0.y > mx) { mx = p0.y; mi = base + 1; }
        if (p0.z > mx) { mx = p0.z; mi = base + 2; }
        if (p0.w > mx) { mx = p0.w; mi = base + 3; }
        if (p1.x > mx) { mx = p1.x; mi = base + 4; }
        if (p1.y > mx) { mx = p1.y; mi = base + 5; }
        if (p1.z > mx) { mx = p1.z; mi = base + 6; }
        if (p1.w > mx) { mx = p1.w; mi = base + 7; }
    }

    // Warp reduction (sum + argmax with first-index tiebreak)
    #pragma unroll
    for (int off = 16; off > 0; off >>= 1) {
        sq += __shfl_down_sync(0xFFFFFFFFu, sq, off);
        float omx = __shfl_down_sync(0xFFFFFFFFu, mx, off);
        int   omi = __shfl_down_sync(0xFFFFFFFFu, mi, off);
        if (omx > mx || (omx == mx && omi < mi)) { mx = omx; mi = omi; }
    }

    __shared__ float s_sq[4];
    __shared__ float s_mx[4];
    __shared__ int   s_mi[4];
    const int wid = tid >> 5, lane = tid & 31;
    if (lane == 0) { s_sq[wid] = sq; s_mx[wid] = mx; s_mi[wid] = mi; }
    __syncthreads();

    if (wid == 0) {
        sq = (lane < 4) ? s_sq[lane] : 0.0f;
        mx = (lane < 4) ? s_mx[lane] : -CUDART_INF_F;
        mi = (lane < 4) ? s_mi[lane] : 0x7FFFFFFF;
        #pragma unroll
        for (int off = 2; off > 0; off >>= 1) {
            sq += __shfl_down_sync(0xFFFFFFFFu, sq, off);
            float omx = __shfl_down_sync(0xFFFFFFFFu, mx, off);
            int   omi = __shfl_down_sync(0xFFFFFFFFu, mi, off);
            if (omx > mx || (omx == mx && omi < mi)) { mx = omx; mi = omi; }
        }

        // ---- Label-loss epilogue, fused: broadcast result to warp 0 ----
        sq = __shfl_sync(0xFFFFFFFFu, sq, 0);
        mx = __shfl_sync(0xFFFFFFFFu, mx, 0);
        mi = __shfl_sync(0xFFFFFFFFu, mi, 0);

        const float* __restrict__ lab = labels + ((size_t)b * K + k) * 11;

        // lanes 0..8: one class-channel gather each at the argmax position
        float part = 0.0f;
        if (lane < C) {
            const float v = __ldg(&lb_preds[((size_t)bs * C + lane) * HW + mi]);
            const float d = v - __ldg(&lab[lane]);
            part = d * d;
        }
        #pragma unroll
        for (int off = 8; off > 0; off >>= 1)
            part += __shfl_down_sync(0xFFFFFFFFu, part, off);

        if (lane == 0) {
            const float gx = __ldg(&lab[9]);
            const float gy = __ldg(&lab[10]);
            const bool valid = (gx >= 0.0f) && (gy >= 0.0f) &&
                               (gx < (float)H) && (gy < (float)W);
            const int x = mi / W;  // m == H == W == 128: pos == idx
            const int y = mi % W;
            const float dx = gx - (float)x;
            const float dy = gy - (float)y;
            const float cf = 1.0f - mx;
            const float lb = valid ? (part + dx * dx + dy * dy + cf * cf) : 0.0f;

            atomicAdd(&out[bs],      sq);  // hm_loss [B,S]
            atomicAdd(&out[BS + bs], lb);  // lb_loss [B,S]
        }
    }
}

extern "C" void kernel_launch(void* const* d_in, const int* in_sizes, int n_in,
                              void* d_out, int out_size) {
    const float* hm_preds = (const float*)d_in[0];  // [B,S,K,H,W]
    const float* lb_preds = (const float*)d_in[1];  // [B,S,C,H,W]
    const float* heatmaps = (const float*)d_in[2];  // [B,K,H,W]
    const float* labels   = (const float*)d_in[3];  // [B,K,11]
    float* out = (float*)d_out;

    kp_zero_kernel<<<1, 2 * BS>>>(out);
    kp_fused_kernel<<<BSK, NT>>>(hm_preds, lb_preds, heatmaps, labels, out);
}